// round 16
// baseline (speedup 1.0000x reference)
#include <cuda_runtime.h>
#include <cstdint>

#define NB 8
#define CB 16
#define HB 256
#define WB 256
#define TOT (NB*CB*HB*WB)   // 8388608
#define IDX_OFF (TOT + 91)

#define TJ 64               // output tile width  (j)
#define TI 8                // output tile height (i)
#define NTHR 128            // 4 warps; warp w -> output rows 2w, 2w+1
#define PCOLS 68            // 66 used (TJ+2 halo), padded
#define PROWS (TI+2)        // 10
#define PSZ (PROWS*PCOLS)
#define NELEM (PROWS*66)    // 660 plane elements
#define KPT 6               // ceil(660/128); k<5 always in range
#define NBUF 8              // power of two -> ring index is & 7
#define SLOTS 512

__device__ float2 g_mm[SLOTS];   // per-block (min,max) partials

// ---------------------------------------------------------------------------
__global__ void __launch_bounds__(256)
minmax_kernel(const float4* __restrict__ x, int n4,
              const float* __restrict__ co,
              const float* __restrict__ filt,
              float* __restrict__ out) {
    if (blockIdx.x == 0) {
        int t = threadIdx.x;
        if (t < 64) out[TOT + t] = co[t];
        if (t < 27) out[TOT + 64 + t] = filt[t];
    }
    float lmin = __int_as_float(0x7f800000);
    float lmax = 0.0f;
    int stride = gridDim.x * blockDim.x;
    for (int i = blockIdx.x * blockDim.x + threadIdx.x; i < n4; i += stride) {
        float4 v = x[i];
        lmin = fminf(lmin, fminf(fminf(v.x, v.y), fminf(v.z, v.w)));
        lmax = fmaxf(lmax, fmaxf(fmaxf(v.x, v.y), fmaxf(v.z, v.w)));
    }
#pragma unroll
    for (int o = 16; o; o >>= 1) {
        lmin = fminf(lmin, __shfl_xor_sync(0xffffffffu, lmin, o));
        lmax = fmaxf(lmax, __shfl_xor_sync(0xffffffffu, lmax, o));
    }
    __shared__ float smin[8], smax[8];
    int w = threadIdx.x >> 5;
    if ((threadIdx.x & 31) == 0) { smin[w] = lmin; smax[w] = lmax; }
    __syncthreads();
    if (threadIdx.x < 8) {
        lmin = smin[threadIdx.x];
        lmax = smax[threadIdx.x];
#pragma unroll
        for (int o = 4; o; o >>= 1) {
            lmin = fminf(lmin, __shfl_xor_sync(0xffu, lmin, o));
            lmax = fmaxf(lmax, __shfl_xor_sync(0xffu, lmax, o));
        }
        if (threadIdx.x == 0) g_mm[blockIdx.x] = make_float2(lmin, lmax);
    }
}

// ---------------------------------------------------------------------------
__device__ __forceinline__ uint32_t smem_u32(const void* p) {
    uint32_t a;
    asm("{ .reg .u64 t; cvta.to.shared.u64 t, %1; cvt.u32.u64 %0, t; }"
        : "=r"(a) : "l"(p));
    return a;
}

// co gather: addr = (w & 0x380) | rbase -> one LOP3, then LDS (bank = lane).
__device__ __forceinline__ float co_gather(uint32_t w, uint32_t rbase) {
    uint32_t a; float v;
    asm("lop3.b32 %0, %1, 0x380, %2, 0xEA;" : "=r"(a) : "r"(w), "r"(rbase));
    asm("ld.shared.f32 %0, [%1];" : "=f"(v) : "r"(a));
    return v;
}

// Packed-pair quantize+pack (bit-identical to the scalar path):
// Markstein exactly-rounded division done as f32x2 (two independent RN
// lanes == two scalar RN ops), then scalar RZ floor-bit extraction.
__device__ __forceinline__ void quant2(
    float x0, float x1,
    unsigned long long xminn2, unsigned long long xmaxn2, unsigned long long rcp2,
    unsigned& pv0, unsigned& pv1)
{
    unsigned long long x2, d2, q02, e2, qq2;
    asm("mov.b64 %0, {%1, %2};" : "=l"(x2) : "f"(x0), "f"(x1));
    asm("add.rn.f32x2 %0, %1, %2;" : "=l"(d2) : "l"(x2), "l"(xminn2));
    asm("mul.rn.f32x2 %0, %1, %2;" : "=l"(q02) : "l"(d2), "l"(rcp2));
    asm("fma.rn.f32x2 %0, %1, %2, %3;" : "=l"(e2) : "l"(xmaxn2), "l"(q02), "l"(d2));
    asm("fma.rn.f32x2 %0, %1, %2, %3;" : "=l"(qq2) : "l"(e2), "l"(rcp2), "l"(q02));
    float qa, qb;
    asm("mov.b64 {%0, %1}, %2;" : "=f"(qa), "=f"(qb) : "l"(qq2));
    unsigned ua = __float_as_uint(__fmaf_rz(qa, 8.0f, 256.0f));
    unsigned ub = __float_as_uint(__fmaf_rz(qb, 8.0f, 256.0f));
    unsigned fa = (ua >> 8) & 0x780u;  fa = (fa == 0x400u) ? 0x780u : fa;
    unsigned fb = (ub >> 8) & 0x780u;  fb = (fb == 0x400u) ? 0x780u : fb;
    pv0 = (__float_as_uint(x0) & ~0x780u) | fa;
    pv1 = (__float_as_uint(x1) & ~0x780u) | fb;
}

// ---------------------------------------------------------------------------
// out[n,c,i,j] = [idx_p<8] * sum_{27} filt * co[idx_p, clamp(idx_nbr,7)] * x_nbr
//
// Packed word: x mantissa bits [9:7] = clamped column (pre-shifted byte
// offset for the 128B column stride), bit [10] = (idx==8) flag.
// co table: 8 rows x 8 cols x 32 lane replicas (8 KB), conflict-free.
//
// Structure: TWO channels/iter, 8-buffer plane ring, staged-register LDGs.
// THIS ROUND: stage LDGs are issued BEFORE __syncthreads (they touch only
// global memory), overlapping global latency with the barrier drain; stage
// loads are unguarded (invalid elems have goff==0, a valid address; the
// zero-masking happens at the smem store); drain/prologue quantization uses
// packed f32x2 Markstein (bit-exact). launch_bounds(128,7) pins regs<=72
// so the 7-block single wave cannot collapse.
// ---------------------------------------------------------------------------
__global__ void __launch_bounds__(NTHR, 7)
cooc_kernel(const float* __restrict__ x,
            const float* __restrict__ co,
            const float* __restrict__ filt,
            float* __restrict__ out) {
    __shared__ __align__(16) unsigned planes[NBUF][PSZ];  // ~21.3 KB
    __shared__ float co_pad[2048 + 256];                  // 8 KB + align pad
    __shared__ float s_red[16];
    __shared__ float s_mm[2];

    const int tid  = threadIdx.x;
    const int lane = tid & 31;
    const int wrp  = tid >> 5;

    const int j0 = blockIdx.x * TJ;
    const int i0 = blockIdx.y * TI;
    const int n  = blockIdx.z;

    // ---- reduce min/max partials ----
    {
        float2 a = g_mm[tid];
        float2 b = g_mm[tid + 128];
        float2 c = g_mm[tid + 256];
        float2 d = g_mm[tid + 384];
        float mn = fminf(fminf(a.x, b.x), fminf(c.x, d.x));
        float mx = fmaxf(fmaxf(a.y, b.y), fmaxf(c.y, d.y));
#pragma unroll
        for (int o = 16; o; o >>= 1) {
            mn = fminf(mn, __shfl_xor_sync(0xffffffffu, mn, o));
            mx = fmaxf(mx, __shfl_xor_sync(0xffffffffu, mx, o));
        }
        if (lane == 0) { s_red[wrp] = mn; s_red[8 + wrp] = mx; }
    }

    // ---- replicated co LUT ----
    uintptr_t gp = (uintptr_t)co_pad;
    float* co_rep = (float*)((gp + 1023) & ~(uintptr_t)1023);
    const uint32_t co_u32 = smem_u32(co_rep);
    for (int e = tid; e < 2048; e += NTHR) {
        int l = e & 31;
        int c = (e >> 5) & 7;
        int r = e >> 8;
        co_rep[r * 256 + c * 32 + l] = co[r * 8 + c];
    }

    __syncthreads();
    if (tid < 2) {
        float v;
        if (tid == 0) v = fminf(fminf(s_red[0], s_red[1]), fminf(s_red[2], s_red[3]));
        else          v = fmaxf(fmaxf(s_red[8], s_red[9]), fmaxf(s_red[10], s_red[11]));
        s_mm[tid] = v;
    }
    __syncthreads();
    const float xmin = s_mm[0];
    const float xmax = s_mm[1];
    const float rcpm = __frcp_rn(xmax);   // RN(1/xmax)

    // packed f32x2 constants ({v, v} duplicates)
    unsigned long long xminn2, xmaxn2, rcp2;
    {
        float nxmin = -xmin, nxmax = -xmax;
        asm("mov.b64 %0, {%1, %1};" : "=l"(xminn2) : "f"(nxmin));
        asm("mov.b64 %0, {%1, %1};" : "=l"(xmaxn2) : "f"(nxmax));
        asm("mov.b64 %0, {%1, %1};" : "=l"(rcp2)   : "f"(rcpm));
    }

    const float* xb = x + (size_t)n * (CB * HB * WB);

    // ---- channel-invariant prefetch geometry ----
    int  goff[KPT];
    int  soff[KPT];
    bool evalid[KPT];
#pragma unroll
    for (int k = 0; k < KPT; k++) {
        int e = tid + 128 * k;
        int r = e / 66;
        int c = e - r * 66;
        int gi = i0 - 1 + r;
        int gj = j0 - 1 + c;
        bool ok = (e < NELEM) && ((unsigned)gi < (unsigned)HB) &&
                  ((unsigned)gj < (unsigned)WB);
        goff[k]   = ok ? (gi * WB + gj) : 0;   // 0 is a VALID address
        soff[k]   = r * PCOLS + c;
        evalid[k] = ok;
    }

    // ---- prologue: stage planes 0..2 unguarded, pack in f32x2 pairs ----
    {
        float s0[KPT], s1[KPT], s2[KPT];
#pragma unroll
        for (int k = 0; k < KPT; k++) {
            s0[k] = xb[goff[k]];
            s1[k] = xb[1 * HB * WB + goff[k]];
            s2[k] = xb[2 * HB * WB + goff[k]];
        }
#pragma unroll
        for (int k = 0; k < KPT; k += 2) {
            unsigned p0a, p0b, p1a, p1b, p2a, p2b;
            quant2(s0[k], s0[k + 1], xminn2, xmaxn2, rcp2, p0a, p0b);
            quant2(s1[k], s1[k + 1], xminn2, xmaxn2, rcp2, p1a, p1b);
            quant2(s2[k], s2[k + 1], xminn2, xmaxn2, rcp2, p2a, p2b);
            // element k (k in {0,2,4}: store index always in range)
            planes[0][soff[k]] = 0u;
            planes[1][soff[k]] = evalid[k] ? p0a : 0u;
            planes[2][soff[k]] = evalid[k] ? p1a : 0u;
            planes[3][soff[k]] = evalid[k] ? p2a : 0u;
            // element k+1 (k+1==5 needs range guard)
            if (k + 1 < 5 || tid + 128 * 5 < NELEM) {
                planes[0][soff[k + 1]] = 0u;
                planes[1][soff[k + 1]] = evalid[k + 1] ? p0b : 0u;
                planes[2][soff[k + 1]] = evalid[k + 1] ? p1b : 0u;
                planes[3][soff[k + 1]] = evalid[k + 1] ? p2b : 0u;
            }
        }
    }

    // ---- filter -> registers (fenced) ----
    float fr[27];
#pragma unroll
    for (int k = 0; k < 27; k++) {
        float v = filt[k];
        asm("mov.f32 %0, %0;" : "+f"(v));
        fr[k] = v;
    }

    const int rowbase = 2 * wrp;
    const int gi0     = i0 + 2 * wrp;
    const int jb      = j0 + 2 * lane;
    const uint32_t lanebase = co_u32 + (lane << 2);

    auto tap3 = [&](float& acc, uint32_t rb, int fo,
                    unsigned p0, unsigned p1, unsigned p2) {
        acc = fmaf(fr[fo + 0], co_gather(p0, rb) * __uint_as_float(p0), acc);
        acc = fmaf(fr[fo + 1], co_gather(p1, rb) * __uint_as_float(p1), acc);
        acc = fmaf(fr[fo + 2], co_gather(p2, rb) * __uint_as_float(p2), acc);
    };

#pragma unroll 1
    for (int it = 0; it < CB / 2; it++) {
        const int ci   = 2 * it;
        const int base = (2 * it) & (NBUF - 1);   // buf of plane ci-1

        // ---- stage LDGs BEFORE the sync (global-only; overlaps barrier) ----
        float sv0[KPT], sv1[KPT];
        const bool do_pref = (it < CB / 2 - 1);
        const bool in1     = (ci + 4 < CB);
        if (do_pref) {
            const float* s0 = xb + (ci + 3) * (HB * WB);      // ci+3 <= 15
            const float* s1 = xb + (in1 ? (ci + 4) : (ci + 3)) * (HB * WB);
#pragma unroll
            for (int k = 0; k < KPT; k++) {
                sv0[k] = s0[goff[k]];     // unguarded: goff valid always
                sv1[k] = s1[goff[k]];
            }
        }

        __syncthreads();

        const int bA = (base + 1) & (NBUF - 1);   // plane ci
        const int bB = (base + 2) & (NBUF - 1);   // plane ci+1

        // ---- centers for both channels ----
        const unsigned* Pa = planes[bA] + rowbase * PCOLS + 2 * lane;
        const unsigned* Pb = planes[bB] + rowbase * PCOLS + 2 * lane;
        uint2 a1  = *(const uint2*)(Pa + 1 * PCOLS);
        uint2 a1h = *(const uint2*)(Pa + 1 * PCOLS + 2);
        uint2 a2  = *(const uint2*)(Pa + 2 * PCOLS);
        uint2 a2h = *(const uint2*)(Pa + 2 * PCOLS + 2);
        uint2 b1  = *(const uint2*)(Pb + 1 * PCOLS);
        uint2 b1h = *(const uint2*)(Pb + 1 * PCOLS + 2);
        uint2 b2  = *(const uint2*)(Pb + 2 * PCOLS);
        uint2 b2h = *(const uint2*)(Pb + 2 * PCOLS + 2);
        const unsigned cw00 = a1.y, cw01 = a1h.x, cw10 = a2.y, cw11 = a2h.x;
        const unsigned dw00 = b1.y, dw01 = b1h.x, dw10 = b2.y, dw11 = b2h.x;
        const uint32_t rb00 = lanebase + ((cw00 & 0x380u) << 3);
        const uint32_t rb01 = lanebase + ((cw01 & 0x380u) << 3);
        const uint32_t rb10 = lanebase + ((cw10 & 0x380u) << 3);
        const uint32_t rb11 = lanebase + ((cw11 & 0x380u) << 3);
        const uint32_t sb00 = lanebase + ((dw00 & 0x380u) << 3);
        const uint32_t sb01 = lanebase + ((dw01 & 0x380u) << 3);
        const uint32_t sb10 = lanebase + ((dw10 & 0x380u) << 3);
        const uint32_t sb11 = lanebase + ((dw11 & 0x380u) << 3);

        float a00 = 0.f, a01 = 0.f, a10 = 0.f, a11 = 0.f;   // channel ci
        float b00 = 0.f, b01 = 0.f, b10 = 0.f, b11 = 0.f;   // channel ci+1

#pragma unroll
        for (int pi = 0; pi < 4; pi++) {      // plane ci-1+pi
            const int bp = (base + pi) & (NBUF - 1);
            const unsigned* P = planes[bp] + rowbase * PCOLS + 2 * lane;
#pragma unroll
            for (int r = 0; r < 4; r++) {
                uint2 A  = *(const uint2*)(P + r * PCOLS);
                uint2 Bv = *(const uint2*)(P + r * PCOLS + 2);
                unsigned w0 = A.x, w1 = A.y, w2 = Bv.x, w3 = Bv.y;
                if (pi <= 2) {                 // channel ci, dc = pi
                    if (r <= 2) {
                        tap3(a00, rb00, pi * 9 + r * 3, w0, w1, w2);
                        tap3(a01, rb01, pi * 9 + r * 3, w1, w2, w3);
                    }
                    if (r >= 1) {
                        tap3(a10, rb10, pi * 9 + (r - 1) * 3, w0, w1, w2);
                        tap3(a11, rb11, pi * 9 + (r - 1) * 3, w1, w2, w3);
                    }
                }
                if (pi >= 1) {                 // channel ci+1, dc = pi-1
                    if (r <= 2) {
                        tap3(b00, sb00, (pi - 1) * 9 + r * 3, w0, w1, w2);
                        tap3(b01, sb01, (pi - 1) * 9 + r * 3, w1, w2, w3);
                    }
                    if (r >= 1) {
                        tap3(b10, sb10, (pi - 1) * 9 + (r - 1) * 3, w0, w1, w2);
                        tap3(b11, sb11, (pi - 1) * 9 + (r - 1) * 3, w1, w2, w3);
                    }
                }
            }
        }

        // ---- stores: channel ci ----
        const int o0 = ((n * CB + ci) * HB + gi0) * WB + jb;
        const int o1 = o0 + WB;
        {
            float2 r0v, r1v;
            r0v.x = (cw00 & 0x400u) ? 0.0f : a00;
            r0v.y = (cw01 & 0x400u) ? 0.0f : a01;
            r1v.x = (cw10 & 0x400u) ? 0.0f : a10;
            r1v.y = (cw11 & 0x400u) ? 0.0f : a11;
            *(float2*)(out + o0) = r0v;
            *(float2*)(out + o1) = r1v;
            out[IDX_OFF + o0]     = (float)(((cw00 >> 7) & 7u) + ((cw00 >> 10) & 1u));
            out[IDX_OFF + o0 + 1] = (float)(((cw01 >> 7) & 7u) + ((cw01 >> 10) & 1u));
            out[IDX_OFF + o1]     = (float)(((cw10 >> 7) & 7u) + ((cw10 >> 10) & 1u));
            out[IDX_OFF + o1 + 1] = (float)(((cw11 >> 7) & 7u) + ((cw11 >> 10) & 1u));
        }
        // ---- stores: channel ci+1 ----
        const int p0 = o0 + HB * WB;
        const int p1 = p0 + WB;
        {
            float2 r0v, r1v;
            r0v.x = (dw00 & 0x400u) ? 0.0f : b00;
            r0v.y = (dw01 & 0x400u) ? 0.0f : b01;
            r1v.x = (dw10 & 0x400u) ? 0.0f : b10;
            r1v.y = (dw11 & 0x400u) ? 0.0f : b11;
            *(float2*)(out + p0) = r0v;
            *(float2*)(out + p1) = r1v;
            out[IDX_OFF + p0]     = (float)(((dw00 >> 7) & 7u) + ((dw00 >> 10) & 1u));
            out[IDX_OFF + p0 + 1] = (float)(((dw01 >> 7) & 7u) + ((dw01 >> 10) & 1u));
            out[IDX_OFF + p1]     = (float)(((dw10 >> 7) & 7u) + ((dw10 >> 10) & 1u));
            out[IDX_OFF + p1 + 1] = (float)(((dw11 >> 7) & 7u) + ((dw11 >> 10) & 1u));
        }

        // ---- drain: pack staged values (f32x2 pairs), store planes ----
        // writes hit bufs base+4, base+5: not read this iteration; next
        // iteration's reads happen after its __syncthreads.
        if (do_pref) {
            unsigned* B4 = planes[(base + 4) & (NBUF - 1)];
            unsigned* B5 = planes[(base + 5) & (NBUF - 1)];
#pragma unroll
            for (int k = 0; k < KPT; k += 2) {
                unsigned q0a, q0b, q1a, q1b;
                quant2(sv0[k], sv0[k + 1], xminn2, xmaxn2, rcp2, q0a, q0b);
                quant2(sv1[k], sv1[k + 1], xminn2, xmaxn2, rcp2, q1a, q1b);
                B4[soff[k]] = evalid[k] ? q0a : 0u;
                B5[soff[k]] = (in1 && evalid[k]) ? q1a : 0u;
                if (k + 1 < 5 || tid + 128 * 5 < NELEM) {
                    B4[soff[k + 1]] = evalid[k + 1] ? q0b : 0u;
                    B5[soff[k + 1]] = (in1 && evalid[k + 1]) ? q1b : 0u;
                }
            }
        }
    }
}

// ---------------------------------------------------------------------------
extern "C" void kernel_launch(void* const* d_in, const int* in_sizes, int n_in,
                              void* d_out, int out_size) {
    const float* x    = (const float*)d_in[0];
    const float* co   = (const float*)d_in[1];
    const float* filt = (const float*)d_in[2];
    float* out        = (float*)d_out;

    minmax_kernel<<<SLOTS, 256>>>((const float4*)x, TOT / 4, co, filt, out);

    dim3 grid(WB / TJ, HB / TI, NB);   // 4 x 32 x 8 = 1024 blocks
    cooc_kernel<<<grid, NTHR>>>(x, co, filt, out);
}

// round 17
// speedup vs baseline: 1.0070x; 1.0070x over previous
#include <cuda_runtime.h>
#include <cstdint>

#define NB 8
#define CB 16
#define HB 256
#define WB 256
#define TOT (NB*CB*HB*WB)   // 8388608
#define IDX_OFF (TOT + 91)

#define TJ 64               // output tile width  (j)
#define TI 8                // output tile height (i)
#define NTHR 128            // 4 warps; warp w -> output rows 2w, 2w+1
#define PCOLS 68            // 66 used (TJ+2 halo), padded
#define PROWS (TI+2)        // 10
#define PSZ (PROWS*PCOLS)
#define NELEM (PROWS*66)    // 660 plane elements
#define KPT 6               // ceil(660/128); k<5 always in range
#define NBUF 8              // power of two -> ring index is & 7
#define SLOTS 512

__device__ float2 g_mm[SLOTS];   // per-block (min,max) partials

// ---------------------------------------------------------------------------
__global__ void __launch_bounds__(256)
minmax_kernel(const float4* __restrict__ x, int n4,
              const float* __restrict__ co,
              const float* __restrict__ filt,
              float* __restrict__ out) {
    if (blockIdx.x == 0) {
        int t = threadIdx.x;
        if (t < 64) out[TOT + t] = co[t];
        if (t < 27) out[TOT + 64 + t] = filt[t];
    }
    float lmin = __int_as_float(0x7f800000);
    float lmax = 0.0f;
    const int stride = gridDim.x * blockDim.x;
    int i = blockIdx.x * blockDim.x + threadIdx.x;
    // 4-way unrolled main loop: 4 independent LDG.128 in flight (MLP=4)
    for (; i + 3 * stride < n4; i += 4 * stride) {
        float4 v0 = x[i];
        float4 v1 = x[i + stride];
        float4 v2 = x[i + 2 * stride];
        float4 v3 = x[i + 3 * stride];
        float mn0 = fminf(fminf(v0.x, v0.y), fminf(v0.z, v0.w));
        float mn1 = fminf(fminf(v1.x, v1.y), fminf(v1.z, v1.w));
        float mn2 = fminf(fminf(v2.x, v2.y), fminf(v2.z, v2.w));
        float mn3 = fminf(fminf(v3.x, v3.y), fminf(v3.z, v3.w));
        float mx0 = fmaxf(fmaxf(v0.x, v0.y), fmaxf(v0.z, v0.w));
        float mx1 = fmaxf(fmaxf(v1.x, v1.y), fmaxf(v1.z, v1.w));
        float mx2 = fmaxf(fmaxf(v2.x, v2.y), fmaxf(v2.z, v2.w));
        float mx3 = fmaxf(fmaxf(v3.x, v3.y), fmaxf(v3.z, v3.w));
        lmin = fminf(lmin, fminf(fminf(mn0, mn1), fminf(mn2, mn3)));
        lmax = fmaxf(lmax, fmaxf(fmaxf(mx0, mx1), fmaxf(mx2, mx3)));
    }
    for (; i < n4; i += stride) {
        float4 v = x[i];
        lmin = fminf(lmin, fminf(fminf(v.x, v.y), fminf(v.z, v.w)));
        lmax = fmaxf(lmax, fmaxf(fmaxf(v.x, v.y), fmaxf(v.z, v.w)));
    }
#pragma unroll
    for (int o = 16; o; o >>= 1) {
        lmin = fminf(lmin, __shfl_xor_sync(0xffffffffu, lmin, o));
        lmax = fmaxf(lmax, __shfl_xor_sync(0xffffffffu, lmax, o));
    }
    __shared__ float smin[8], smax[8];
    int w = threadIdx.x >> 5;
    if ((threadIdx.x & 31) == 0) { smin[w] = lmin; smax[w] = lmax; }
    __syncthreads();
    if (threadIdx.x < 8) {
        lmin = smin[threadIdx.x];
        lmax = smax[threadIdx.x];
#pragma unroll
        for (int o = 4; o; o >>= 1) {
            lmin = fminf(lmin, __shfl_xor_sync(0xffu, lmin, o));
            lmax = fmaxf(lmax, __shfl_xor_sync(0xffu, lmax, o));
        }
        if (threadIdx.x == 0) g_mm[blockIdx.x] = make_float2(lmin, lmax);
    }
}

// ---------------------------------------------------------------------------
__device__ __forceinline__ uint32_t smem_u32(const void* p) {
    uint32_t a;
    asm("{ .reg .u64 t; cvta.to.shared.u64 t, %1; cvt.u32.u64 %0, t; }"
        : "=r"(a) : "l"(p));
    return a;
}

// co gather: addr = (w & 0x380) | rbase -> one LOP3, then LDS (bank = lane).
__device__ __forceinline__ float co_gather(uint32_t w, uint32_t rbase) {
    uint32_t a; float v;
    asm("lop3.b32 %0, %1, 0x380, %2, 0xEA;" : "=r"(a) : "r"(w), "r"(rbase));
    asm("ld.shared.f32 %0, [%1];" : "=f"(v) : "r"(a));
    return v;
}

// Packed-pair quantize+pack (bit-identical to the scalar path):
// Markstein exactly-rounded division done as f32x2 (two independent RN
// lanes == two scalar RN ops), then scalar RZ floor-bit extraction.
__device__ __forceinline__ void quant2(
    float x0, float x1,
    unsigned long long xminn2, unsigned long long xmaxn2, unsigned long long rcp2,
    unsigned& pv0, unsigned& pv1)
{
    unsigned long long x2, d2, q02, e2, qq2;
    asm("mov.b64 %0, {%1, %2};" : "=l"(x2) : "f"(x0), "f"(x1));
    asm("add.rn.f32x2 %0, %1, %2;" : "=l"(d2) : "l"(x2), "l"(xminn2));
    asm("mul.rn.f32x2 %0, %1, %2;" : "=l"(q02) : "l"(d2), "l"(rcp2));
    asm("fma.rn.f32x2 %0, %1, %2, %3;" : "=l"(e2) : "l"(xmaxn2), "l"(q02), "l"(d2));
    asm("fma.rn.f32x2 %0, %1, %2, %3;" : "=l"(qq2) : "l"(e2), "l"(rcp2), "l"(q02));
    float qa, qb;
    asm("mov.b64 {%0, %1}, %2;" : "=f"(qa), "=f"(qb) : "l"(qq2));
    unsigned ua = __float_as_uint(__fmaf_rz(qa, 8.0f, 256.0f));
    unsigned ub = __float_as_uint(__fmaf_rz(qb, 8.0f, 256.0f));
    unsigned fa = (ua >> 8) & 0x780u;  fa = (fa == 0x400u) ? 0x780u : fa;
    unsigned fb = (ub >> 8) & 0x780u;  fb = (fb == 0x400u) ? 0x780u : fb;
    pv0 = (__float_as_uint(x0) & ~0x780u) | fa;
    pv1 = (__float_as_uint(x1) & ~0x780u) | fb;
}

// ---------------------------------------------------------------------------
// out[n,c,i,j] = [idx_p<8] * sum_{27} filt * co[idx_p, clamp(idx_nbr,7)] * x_nbr
//
// Packed word: x mantissa bits [9:7] = clamped column (pre-shifted byte
// offset for the 128B column stride), bit [10] = (idx==8) flag.
// co table: 8 rows x 8 cols x 32 lane replicas (8 KB), conflict-free.
//
// Structure: TWO channels/iter, 8-buffer ring, stage-LDGs-before-sync.
// THIS ROUND: center words are NOT loaded separately -- the tap-loop loads
// at (pi=1, r=1/2) and (pi=2, r=1/2) are the same addresses, so those four
// row loads are hoisted, centers derived from them, and the registers reused
// inside the fully unrolled tap loop (-8 LDS.64, -16 wavefronts per iter).
// ---------------------------------------------------------------------------
__global__ void __launch_bounds__(NTHR, 7)
cooc_kernel(const float* __restrict__ x,
            const float* __restrict__ co,
            const float* __restrict__ filt,
            float* __restrict__ out) {
    __shared__ __align__(16) unsigned planes[NBUF][PSZ];  // ~21.3 KB
    __shared__ float co_pad[2048 + 256];                  // 8 KB + align pad
    __shared__ float s_red[16];
    __shared__ float s_mm[2];

    const int tid  = threadIdx.x;
    const int lane = tid & 31;
    const int wrp  = tid >> 5;

    const int j0 = blockIdx.x * TJ;
    const int i0 = blockIdx.y * TI;
    const int n  = blockIdx.z;

    // ---- reduce min/max partials ----
    {
        float2 a = g_mm[tid];
        float2 b = g_mm[tid + 128];
        float2 c = g_mm[tid + 256];
        float2 d = g_mm[tid + 384];
        float mn = fminf(fminf(a.x, b.x), fminf(c.x, d.x));
        float mx = fmaxf(fmaxf(a.y, b.y), fmaxf(c.y, d.y));
#pragma unroll
        for (int o = 16; o; o >>= 1) {
            mn = fminf(mn, __shfl_xor_sync(0xffffffffu, mn, o));
            mx = fmaxf(mx, __shfl_xor_sync(0xffffffffu, mx, o));
        }
        if (lane == 0) { s_red[wrp] = mn; s_red[8 + wrp] = mx; }
    }

    // ---- replicated co LUT ----
    uintptr_t gp = (uintptr_t)co_pad;
    float* co_rep = (float*)((gp + 1023) & ~(uintptr_t)1023);
    const uint32_t co_u32 = smem_u32(co_rep);
    for (int e = tid; e < 2048; e += NTHR) {
        int l = e & 31;
        int c = (e >> 5) & 7;
        int r = e >> 8;
        co_rep[r * 256 + c * 32 + l] = co[r * 8 + c];
    }

    __syncthreads();
    if (tid < 2) {
        float v;
        if (tid == 0) v = fminf(fminf(s_red[0], s_red[1]), fminf(s_red[2], s_red[3]));
        else          v = fmaxf(fmaxf(s_red[8], s_red[9]), fmaxf(s_red[10], s_red[11]));
        s_mm[tid] = v;
    }
    __syncthreads();
    const float xmin = s_mm[0];
    const float xmax = s_mm[1];
    const float rcpm = __frcp_rn(xmax);   // RN(1/xmax)

    // packed f32x2 constants ({v, v} duplicates)
    unsigned long long xminn2, xmaxn2, rcp2;
    {
        float nxmin = -xmin, nxmax = -xmax;
        asm("mov.b64 %0, {%1, %1};" : "=l"(xminn2) : "f"(nxmin));
        asm("mov.b64 %0, {%1, %1};" : "=l"(xmaxn2) : "f"(nxmax));
        asm("mov.b64 %0, {%1, %1};" : "=l"(rcp2)   : "f"(rcpm));
    }

    const float* xb = x + (size_t)n * (CB * HB * WB);

    // ---- channel-invariant prefetch geometry ----
    int  goff[KPT];
    int  soff[KPT];
    bool evalid[KPT];
#pragma unroll
    for (int k = 0; k < KPT; k++) {
        int e = tid + 128 * k;
        int r = e / 66;
        int c = e - r * 66;
        int gi = i0 - 1 + r;
        int gj = j0 - 1 + c;
        bool ok = (e < NELEM) && ((unsigned)gi < (unsigned)HB) &&
                  ((unsigned)gj < (unsigned)WB);
        goff[k]   = ok ? (gi * WB + gj) : 0;   // 0 is a VALID address
        soff[k]   = r * PCOLS + c;
        evalid[k] = ok;
    }

    // ---- prologue: stage planes 0..2 unguarded, pack in f32x2 pairs ----
    {
        float s0[KPT], s1[KPT], s2[KPT];
#pragma unroll
        for (int k = 0; k < KPT; k++) {
            s0[k] = xb[goff[k]];
            s1[k] = xb[1 * HB * WB + goff[k]];
            s2[k] = xb[2 * HB * WB + goff[k]];
        }
#pragma unroll
        for (int k = 0; k < KPT; k += 2) {
            unsigned p0a, p0b, p1a, p1b, p2a, p2b;
            quant2(s0[k], s0[k + 1], xminn2, xmaxn2, rcp2, p0a, p0b);
            quant2(s1[k], s1[k + 1], xminn2, xmaxn2, rcp2, p1a, p1b);
            quant2(s2[k], s2[k + 1], xminn2, xmaxn2, rcp2, p2a, p2b);
            planes[0][soff[k]] = 0u;
            planes[1][soff[k]] = evalid[k] ? p0a : 0u;
            planes[2][soff[k]] = evalid[k] ? p1a : 0u;
            planes[3][soff[k]] = evalid[k] ? p2a : 0u;
            if (k + 1 < 5 || tid + 128 * 5 < NELEM) {
                planes[0][soff[k + 1]] = 0u;
                planes[1][soff[k + 1]] = evalid[k + 1] ? p0b : 0u;
                planes[2][soff[k + 1]] = evalid[k + 1] ? p1b : 0u;
                planes[3][soff[k + 1]] = evalid[k + 1] ? p2b : 0u;
            }
        }
    }

    // ---- filter -> registers (fenced) ----
    float fr[27];
#pragma unroll
    for (int k = 0; k < 27; k++) {
        float v = filt[k];
        asm("mov.f32 %0, %0;" : "+f"(v));
        fr[k] = v;
    }

    const int rowbase = 2 * wrp;
    const int gi0     = i0 + 2 * wrp;
    const int jb      = j0 + 2 * lane;
    const uint32_t lanebase = co_u32 + (lane << 2);

    auto tap3 = [&](float& acc, uint32_t rb, int fo,
                    unsigned p0, unsigned p1, unsigned p2) {
        acc = fmaf(fr[fo + 0], co_gather(p0, rb) * __uint_as_float(p0), acc);
        acc = fmaf(fr[fo + 1], co_gather(p1, rb) * __uint_as_float(p1), acc);
        acc = fmaf(fr[fo + 2], co_gather(p2, rb) * __uint_as_float(p2), acc);
    };

#pragma unroll 1
    for (int it = 0; it < CB / 2; it++) {
        const int ci   = 2 * it;
        const int base = (2 * it) & (NBUF - 1);   // buf of plane ci-1

        // ---- stage LDGs BEFORE the sync (global-only; overlaps barrier) ----
        float sv0[KPT], sv1[KPT];
        const bool do_pref = (it < CB / 2 - 1);
        const bool in1     = (ci + 4 < CB);
        if (do_pref) {
            const float* s0 = xb + (ci + 3) * (HB * WB);      // ci+3 <= 15
#pragma unroll
            for (int k = 0; k < KPT; k++)
                sv0[k] = s0[goff[k]];     // unguarded: goff valid always
            if (in1) {
                const float* s1 = xb + (ci + 4) * (HB * WB);
#pragma unroll
                for (int k = 0; k < KPT; k++)
                    sv1[k] = s1[goff[k]];
            }
        }

        __syncthreads();

        const int bA = (base + 1) & (NBUF - 1);   // plane ci
        const int bB = (base + 2) & (NBUF - 1);   // plane ci+1

        // ---- hoisted row loads (rows 1,2 of planes bA,bB); these double as
        //      the (pi,r) = (1,1),(1,2),(2,1),(2,2) tap-loop loads ----
        const unsigned* Pa = planes[bA] + rowbase * PCOLS + 2 * lane;
        const unsigned* Pb = planes[bB] + rowbase * PCOLS + 2 * lane;
        const uint2 PA1  = *(const uint2*)(Pa + 1 * PCOLS);
        const uint2 PA1h = *(const uint2*)(Pa + 1 * PCOLS + 2);
        const uint2 PA2  = *(const uint2*)(Pa + 2 * PCOLS);
        const uint2 PA2h = *(const uint2*)(Pa + 2 * PCOLS + 2);
        const uint2 PB1  = *(const uint2*)(Pb + 1 * PCOLS);
        const uint2 PB1h = *(const uint2*)(Pb + 1 * PCOLS + 2);
        const uint2 PB2  = *(const uint2*)(Pb + 2 * PCOLS);
        const uint2 PB2h = *(const uint2*)(Pb + 2 * PCOLS + 2);

        const unsigned cw00 = PA1.y, cw01 = PA1h.x, cw10 = PA2.y, cw11 = PA2h.x;
        const unsigned dw00 = PB1.y, dw01 = PB1h.x, dw10 = PB2.y, dw11 = PB2h.x;
        const uint32_t rb00 = lanebase + ((cw00 & 0x380u) << 3);
        const uint32_t rb01 = lanebase + ((cw01 & 0x380u) << 3);
        const uint32_t rb10 = lanebase + ((cw10 & 0x380u) << 3);
        const uint32_t rb11 = lanebase + ((cw11 & 0x380u) << 3);
        const uint32_t sb00 = lanebase + ((dw00 & 0x380u) << 3);
        const uint32_t sb01 = lanebase + ((dw01 & 0x380u) << 3);
        const uint32_t sb10 = lanebase + ((dw10 & 0x380u) << 3);
        const uint32_t sb11 = lanebase + ((dw11 & 0x380u) << 3);

        float a00 = 0.f, a01 = 0.f, a10 = 0.f, a11 = 0.f;   // channel ci
        float b00 = 0.f, b01 = 0.f, b10 = 0.f, b11 = 0.f;   // channel ci+1

#pragma unroll
        for (int pi = 0; pi < 4; pi++) {      // plane ci-1+pi
            const int bp = (base + pi) & (NBUF - 1);
            const unsigned* P = planes[bp] + rowbase * PCOLS + 2 * lane;
#pragma unroll
            for (int r = 0; r < 4; r++) {
                uint2 A, Bv;
                if (pi == 1 && r == 1)      { A = PA1; Bv = PA1h; }
                else if (pi == 1 && r == 2) { A = PA2; Bv = PA2h; }
                else if (pi == 2 && r == 1) { A = PB1; Bv = PB1h; }
                else if (pi == 2 && r == 2) { A = PB2; Bv = PB2h; }
                else {
                    A  = *(const uint2*)(P + r * PCOLS);
                    Bv = *(const uint2*)(P + r * PCOLS + 2);
                }
                unsigned w0 = A.x, w1 = A.y, w2 = Bv.x, w3 = Bv.y;
                if (pi <= 2) {                 // channel ci, dc = pi
                    if (r <= 2) {
                        tap3(a00, rb00, pi * 9 + r * 3, w0, w1, w2);
                        tap3(a01, rb01, pi * 9 + r * 3, w1, w2, w3);
                    }
                    if (r >= 1) {
                        tap3(a10, rb10, pi * 9 + (r - 1) * 3, w0, w1, w2);
                        tap3(a11, rb11, pi * 9 + (r - 1) * 3, w1, w2, w3);
                    }
                }
                if (pi >= 1) {                 // channel ci+1, dc = pi-1
                    if (r <= 2) {
                        tap3(b00, sb00, (pi - 1) * 9 + r * 3, w0, w1, w2);
                        tap3(b01, sb01, (pi - 1) * 9 + r * 3, w1, w2, w3);
                    }
                    if (r >= 1) {
                        tap3(b10, sb10, (pi - 1) * 9 + (r - 1) * 3, w0, w1, w2);
                        tap3(b11, sb11, (pi - 1) * 9 + (r - 1) * 3, w1, w2, w3);
                    }
                }
            }
        }

        // ---- stores: channel ci ----
        const int o0 = ((n * CB + ci) * HB + gi0) * WB + jb;
        const int o1 = o0 + WB;
        {
            float2 r0v, r1v;
            r0v.x = (cw00 & 0x400u) ? 0.0f : a00;
            r0v.y = (cw01 & 0x400u) ? 0.0f : a01;
            r1v.x = (cw10 & 0x400u) ? 0.0f : a10;
            r1v.y = (cw11 & 0x400u) ? 0.0f : a11;
            *(float2*)(out + o0) = r0v;
            *(float2*)(out + o1) = r1v;
            out[IDX_OFF + o0]     = (float)(((cw00 >> 7) & 7u) + ((cw00 >> 10) & 1u));
            out[IDX_OFF + o0 + 1] = (float)(((cw01 >> 7) & 7u) + ((cw01 >> 10) & 1u));
            out[IDX_OFF + o1]     = (float)(((cw10 >> 7) & 7u) + ((cw10 >> 10) & 1u));
            out[IDX_OFF + o1 + 1] = (float)(((cw11 >> 7) & 7u) + ((cw11 >> 10) & 1u));
        }
        // ---- stores: channel ci+1 ----
        const int p0 = o0 + HB * WB;
        const int p1 = p0 + WB;
        {
            float2 r0v, r1v;
            r0v.x = (dw00 & 0x400u) ? 0.0f : b00;
            r0v.y = (dw01 & 0x400u) ? 0.0f : b01;
            r1v.x = (dw10 & 0x400u) ? 0.0f : b10;
            r1v.y = (dw11 & 0x400u) ? 0.0f : b11;
            *(float2*)(out + p0) = r0v;
            *(float2*)(out + p1) = r1v;
            out[IDX_OFF + p0]     = (float)(((dw00 >> 7) & 7u) + ((dw00 >> 10) & 1u));
            out[IDX_OFF + p0 + 1] = (float)(((dw01 >> 7) & 7u) + ((dw01 >> 10) & 1u));
            out[IDX_OFF + p1]     = (float)(((dw10 >> 7) & 7u) + ((dw10 >> 10) & 1u));
            out[IDX_OFF + p1 + 1] = (float)(((dw11 >> 7) & 7u) + ((dw11 >> 10) & 1u));
        }

        // ---- drain: pack staged values (f32x2 pairs), store planes ----
        // writes hit bufs base+4, base+5: not read this iteration; next
        // iteration's reads happen after its __syncthreads.
        if (do_pref) {
            unsigned* B4 = planes[(base + 4) & (NBUF - 1)];
            unsigned* B5 = planes[(base + 5) & (NBUF - 1)];
#pragma unroll
            for (int k = 0; k < KPT; k += 2) {
                unsigned q0a, q0b, q1a, q1b;
                quant2(sv0[k], sv0[k + 1], xminn2, xmaxn2, rcp2, q0a, q0b);
                if (in1) quant2(sv1[k], sv1[k + 1], xminn2, xmaxn2, rcp2, q1a, q1b);
                else { q1a = 0u; q1b = 0u; }
                B4[soff[k]] = evalid[k] ? q0a : 0u;
                B5[soff[k]] = (in1 && evalid[k]) ? q1a : 0u;
                if (k + 1 < 5 || tid + 128 * 5 < NELEM) {
                    B4[soff[k + 1]] = evalid[k + 1] ? q0b : 0u;
                    B5[soff[k + 1]] = (in1 && evalid[k + 1]) ? q1b : 0u;
                }
            }
        }
    }
}

// ---------------------------------------------------------------------------
extern "C" void kernel_launch(void* const* d_in, const int* in_sizes, int n_in,
                              void* d_out, int out_size) {
    const float* x    = (const float*)d_in[0];
    const float* co   = (const float*)d_in[1];
    const float* filt = (const float*)d_in[2];
    float* out        = (float*)d_out;

    minmax_kernel<<<SLOTS, 256>>>((const float4*)x, TOT / 4, co, filt, out);

    dim3 grid(WB / TJ, HB / TI, NB);   // 4 x 32 x 8 = 1024 blocks
    cooc_kernel<<<grid, NTHR>>>(x, co, filt, out);
}